// round 15
// baseline (speedup 1.0000x reference)
#include <cuda_runtime.h>
#include <cuda_bf16.h>
#include <cuda_fp16.h>
#include <cstdint>
#include <cstddef>

// ---------------- problem constants ----------------
#define BB      8
#define TT      8
#define NN      196
#define DD      768
#define HH      12
#define HD      64
#define TNTOK   (TT*NN)            // 1568
#define MROWS   (BB*TNTOK)         // 12544
#define QKVCOLS (3*DD)             // 2304

// ---------------- scratch ----------------
__device__ __nv_bfloat16 g_xh[(size_t)MROWS * DD];
__device__ __nv_bfloat16 g_xl[(size_t)MROWS * DD];
__device__ __nv_bfloat16 g_wqkvT_h[(size_t)QKVCOLS * DD];
__device__ __nv_bfloat16 g_wqkvT_l[(size_t)QKVCOLS * DD];
__device__ __nv_bfloat16 g_wprojT_h[(size_t)DD * DD];
__device__ __nv_bfloat16 g_wprojT_l[(size_t)DD * DD];
__device__ __nv_bfloat16 g_qkvh[(size_t)MROWS * QKVCOLS];
__device__ __nv_bfloat16 g_qkvl[(size_t)MROWS * QKVCOLS];
__device__ __nv_bfloat16 g_yh[(size_t)MROWS * DD];
__device__ __nv_bfloat16 g_yl[(size_t)MROWS * DD];

// ---------------- helpers ----------------
__device__ __forceinline__ uint32_t smem_u32(const void* p) {
    uint32_t a;
    asm("{ .reg .u64 t; cvta.to.shared.u64 t, %1; cvt.u32.u64 %0, t; }" : "=r"(a) : "l"(p));
    return a;
}
__device__ __forceinline__ void mma16816(float* c, const uint32_t* a, const uint32_t* b) {
    asm volatile(
        "mma.sync.aligned.m16n8k16.row.col.f32.bf16.bf16.f32 "
        "{%0,%1,%2,%3}, {%4,%5,%6,%7}, {%8,%9}, {%0,%1,%2,%3};"
        : "+f"(c[0]), "+f"(c[1]), "+f"(c[2]), "+f"(c[3])
        : "r"(a[0]), "r"(a[1]), "r"(a[2]), "r"(a[3]), "r"(b[0]), "r"(b[1]));
}
__device__ __forceinline__ void mma16816h(float* c, const uint32_t* a, const uint32_t* b) {
    asm volatile(
        "mma.sync.aligned.m16n8k16.row.col.f32.f16.f16.f32 "
        "{%0,%1,%2,%3}, {%4,%5,%6,%7}, {%8,%9}, {%0,%1,%2,%3};"
        : "+f"(c[0]), "+f"(c[1]), "+f"(c[2]), "+f"(c[3])
        : "r"(a[0]), "r"(a[1]), "r"(a[2]), "r"(a[3]), "r"(b[0]), "r"(b[1]));
}
__device__ __forceinline__ void ldsm4(uint32_t& r0, uint32_t& r1, uint32_t& r2, uint32_t& r3,
                                      uint32_t addr) {
    asm volatile("ldmatrix.sync.aligned.m8n8.x4.shared.b16 {%0,%1,%2,%3}, [%4];"
        : "=r"(r0), "=r"(r1), "=r"(r2), "=r"(r3) : "r"(addr));
}
#define CP_ASYNC16(dst, src) \
    asm volatile("cp.async.cg.shared.global [%0], [%1], 16;" :: "r"(dst), "l"(src))
#define CP_COMMIT() asm volatile("cp.async.commit_group;" ::: "memory")

__device__ __forceinline__ uint32_t pack_bf16x2(float lo, float hi) {
    uint32_t d;
    asm("cvt.rn.bf16x2.f32 %0, %1, %2;" : "=r"(d) : "f"(hi), "f"(lo));
    return d;
}
__device__ __forceinline__ uint32_t exp2_f16x2(float lo, float hi) {
    uint32_t t, d;
    asm("cvt.rn.f16x2.f32 %0, %1, %2;" : "=r"(t) : "f"(hi), "f"(lo));
    asm("ex2.approx.f16x2 %0, %1;" : "=r"(d) : "r"(t));
    return d;
}
__device__ __forceinline__ float exp2_f32(float x) {
    float d;
    asm("ex2.approx.f32 %0, %1;" : "=f"(d) : "f"(x));
    return d;
}

// ---------------- prep: fp32 -> bf16 hi/lo split (elementwise) --------------
__global__ __launch_bounds__(256) void convert_split(
    const float* __restrict__ src, __nv_bfloat16* __restrict__ dh,
    __nv_bfloat16* __restrict__ dl, int n4)
{
    int i = blockIdx.x * blockDim.x + threadIdx.x;
    if (i >= n4) return;
    float4 v = *(const float4*)(src + (size_t)i * 4);
    __nv_bfloat16 h0 = __float2bfloat16(v.x), h1 = __float2bfloat16(v.y);
    __nv_bfloat16 h2 = __float2bfloat16(v.z), h3 = __float2bfloat16(v.w);
    __nv_bfloat16 l0 = __float2bfloat16(v.x - __bfloat162float(h0));
    __nv_bfloat16 l1 = __float2bfloat16(v.y - __bfloat162float(h1));
    __nv_bfloat16 l2 = __float2bfloat16(v.z - __bfloat162float(h2));
    __nv_bfloat16 l3 = __float2bfloat16(v.w - __bfloat162float(h3));
    *(__nv_bfloat162*)(dh + (size_t)i * 4 + 0) = {h0, h1};
    *(__nv_bfloat162*)(dh + (size_t)i * 4 + 2) = {h2, h3};
    *(__nv_bfloat162*)(dl + (size_t)i * 4 + 0) = {l0, l1};
    *(__nv_bfloat162*)(dl + (size_t)i * 4 + 2) = {l2, l3};
}

// ---------------- prep: transpose weights [K][N] -> [N][K] + hi/lo split ----
__global__ __launch_bounds__(256) void transpose_split(
    const float* __restrict__ src, __nv_bfloat16* __restrict__ dh,
    __nv_bfloat16* __restrict__ dl, int K, int N)
{
    __shared__ float t[32][33];
    int n0 = blockIdx.x * 32, k0 = blockIdx.y * 32;
    int tx = threadIdx.x, ty = threadIdx.y;   // block (32, 8)
    #pragma unroll
    for (int j = ty; j < 32; j += 8)
        t[j][tx] = src[(size_t)(k0 + j) * N + n0 + tx];
    __syncthreads();
    #pragma unroll
    for (int j = ty; j < 32; j += 8) {
        float v = t[tx][j];
        __nv_bfloat16 h = __float2bfloat16(v);
        __nv_bfloat16 l = __float2bfloat16(v - __bfloat162float(h));
        size_t o = (size_t)(n0 + j) * K + k0 + tx;
        dh[o] = h; dl[o] = l;
    }
}

// ---------------- split-bf16 HMMA GEMM (r13 mainloop; optional split-out) ----
#define G_BK        32
#define G_ROWB      80
#define G_TILE_B    (128 * G_ROWB)          // 10240 B
#define G_STAGE_B   (4 * G_TILE_B)          // 40960 B
#define G_SMEM      (2 * G_STAGE_B)         // 81920 B

__global__ __launch_bounds__(128, 2) void gemm_split_hmma(
    const __nv_bfloat16* __restrict__ Ah, const __nv_bfloat16* __restrict__ Al,
    const __nv_bfloat16* __restrict__ Bh, const __nv_bfloat16* __restrict__ Bl,
    const float* __restrict__ bias, float* __restrict__ C,
    __nv_bfloat16* __restrict__ Ch, __nv_bfloat16* __restrict__ Cl,
    int Ncols, int K)
{
    extern __shared__ char sm[];
    const int tid  = threadIdx.x;
    const int lane = tid & 31;
    const int wid  = tid >> 5;
    const int warp_m = wid >> 1;
    const int warp_n = wid & 1;
    const int g   = lane >> 2;
    const int tig = lane & 3;

    const size_t arow0 = (size_t)blockIdx.y * 128;
    const size_t brow0 = (size_t)blockIdx.x * 128;

    const __nv_bfloat16* gA[4] = {
        Ah + arow0 * K, Al + arow0 * K, Bh + brow0 * K, Bl + brow0 * K };

    const int lrow = tid >> 2;
    const int c16  = tid & 3;
    auto load_stage = [&](int s, int k0) {
        char* base = sm + s * G_STAGE_B;
        #pragma unroll
        for (int i = 0; i < 16; i++) {
            const int t   = i >> 2;
            const int row = (i & 3) * 32 + lrow;
            const __nv_bfloat16* src = gA[t] + (size_t)row * K + k0 + c16 * 8;
            uint32_t dst = smem_u32(base + t * G_TILE_B + row * G_ROWB + c16 * 16);
            CP_ASYNC16(dst, src);
        }
        CP_COMMIT();
    };

    const uint32_t aoff = (uint32_t)((warp_m * 64 + (lane & 15)) * G_ROWB
                                     + (lane >> 4) * 16);
    const uint32_t boff = (uint32_t)((warp_n * 64 + ((lane >> 4) << 3) + (lane & 7)) * G_ROWB
                                     + ((lane >> 3) & 1) * 16);
    const uint32_t smbu = smem_u32(sm);

    float acc[4][8][4];
    #pragma unroll
    for (int mt = 0; mt < 4; mt++)
        #pragma unroll
        for (int nt = 0; nt < 8; nt++)
            #pragma unroll
            for (int i = 0; i < 4; i++) acc[mt][nt][i] = 0.f;

    load_stage(0, 0);

    const int KT = K / G_BK;
    for (int kt = 0; kt < KT; kt++) {
        if (kt + 1 < KT) {
            load_stage((kt + 1) & 1, (kt + 1) * G_BK);
            asm volatile("cp.async.wait_group 1;" ::: "memory");
        } else {
            asm volatile("cp.async.wait_group 0;" ::: "memory");
        }
        __syncthreads();

        const uint32_t sbu  = smbu + (kt & 1) * G_STAGE_B;
        const uint32_t sAhU = sbu + 0 * G_TILE_B + aoff;
        const uint32_t sAlU = sbu + 1 * G_TILE_B + aoff;
        const uint32_t sBhU = sbu + 2 * G_TILE_B + boff;
        const uint32_t sBlU = sbu + 3 * G_TILE_B + boff;

        #pragma unroll
        for (int ks = 0; ks < 2; ks++) {
            const uint32_t ksb = (uint32_t)(ks * 32);
            uint32_t bh[4][4], bl[4][4];
            #pragma unroll
            for (int np = 0; np < 4; np++) {
                ldsm4(bh[np][0], bh[np][1], bh[np][2], bh[np][3],
                      sBhU + np * (16 * G_ROWB) + ksb);
                ldsm4(bl[np][0], bl[np][1], bl[np][2], bl[np][3],
                      sBlU + np * (16 * G_ROWB) + ksb);
            }
            uint32_t ah[2][4], al[2][4];
            ldsm4(ah[0][0], ah[0][1], ah[0][2], ah[0][3], sAhU + ksb);
            ldsm4(al[0][0], al[0][1], al[0][2], al[0][3], sAlU + ksb);
            #pragma unroll
            for (int mt = 0; mt < 4; mt++) {
                const int cur = mt & 1, nxt = cur ^ 1;
                if (mt < 3) {
                    ldsm4(ah[nxt][0], ah[nxt][1], ah[nxt][2], ah[nxt][3],
                          sAhU + (mt + 1) * (16 * G_ROWB) + ksb);
                    ldsm4(al[nxt][0], al[nxt][1], al[nxt][2], al[nxt][3],
                          sAlU + (mt + 1) * (16 * G_ROWB) + ksb);
                }
                #pragma unroll
                for (int np = 0; np < 4; np++) {
                    mma16816(acc[mt][2 * np + 0], ah[cur], &bh[np][0]);
                    mma16816(acc[mt][2 * np + 1], ah[cur], &bh[np][2]);
                }
                #pragma unroll
                for (int np = 0; np < 4; np++) {
                    mma16816(acc[mt][2 * np + 0], ah[cur], &bl[np][0]);
                    mma16816(acc[mt][2 * np + 1], ah[cur], &bl[np][2]);
                }
                #pragma unroll
                for (int np = 0; np < 4; np++) {
                    mma16816(acc[mt][2 * np + 0], al[cur], &bh[np][0]);
                    mma16816(acc[mt][2 * np + 1], al[cur], &bh[np][2]);
                }
            }
        }
        __syncthreads();
    }

    const size_t col0 = (size_t)blockIdx.x * 128 + warp_n * 64;
    if (Ch) {
        // split bf16 hi/lo output (for qkv buffer)
        #pragma unroll
        for (int mt = 0; mt < 4; mt++) {
            size_t row = arow0 + warp_m * 64 + mt * 16 + g;
            #pragma unroll
            for (int nt = 0; nt < 8; nt++) {
                size_t col = col0 + nt * 8 + tig * 2;
                #pragma unroll
                for (int half = 0; half < 2; half++) {
                    size_t r = row + half * 8;
                    float v0 = acc[mt][nt][half * 2 + 0];
                    float v1 = acc[mt][nt][half * 2 + 1];
                    __nv_bfloat16 h0 = __float2bfloat16(v0);
                    __nv_bfloat16 h1 = __float2bfloat16(v1);
                    *(uint32_t*)(Ch + r * Ncols + col) = pack_bf16x2(v0, v1);
                    *(uint32_t*)(Cl + r * Ncols + col) =
                        pack_bf16x2(v0 - __bfloat162float(h0), v1 - __bfloat162float(h1));
                }
            }
        }
    } else {
        #pragma unroll
        for (int mt = 0; mt < 4; mt++) {
            size_t row = arow0 + warp_m * 64 + mt * 16 + g;
            #pragma unroll
            for (int nt = 0; nt < 8; nt++) {
                size_t col = col0 + nt * 8 + tig * 2;
                float b0 = 0.f, b1 = 0.f;
                if (bias) { b0 = bias[col]; b1 = bias[col + 1]; }
                float2 v0 = { acc[mt][nt][0] + b0, acc[mt][nt][1] + b1 };
                float2 v1 = { acc[mt][nt][2] + b0, acc[mt][nt][3] + b1 };
                *(float2*)(C + row * Ncols + col)       = v0;
                *(float2*)(C + (row + 8) * Ncols + col) = v1;
            }
        }
    }
}

// ---------------- HMMA attention: 224 thr, 2 tiles/warp, 2 CTA/SM target ----
// qkv comes in pre-split (hi/lo bf16) from the GEMM epilogue: K staging is a
// raw copy, Q fragments load directly, V = f16(hi+lo). Register budget 144
// (224thr x 2 CTA) enforced by launch_bounds.
#define AT_THREADS 224
#define KH_STR   72            // K hi/lo row stride (bf16 units)
#define VT_STR   216           // V^T row stride (f16 units)
#define AT_KPAD  208
#define SM_KL_U  (AT_KPAD * KH_STR)
#define VTH_BYTE (2 * 2 * AT_KPAD * KH_STR)          // 59904
#define VPART_BYTE (VTH_BYTE + 2 * 72 * VT_STR)      // +31104 = 91008
#define VMEAN_BYTE (VPART_BYTE + 2 * 64 * 4)         // +512
#define AT_SMEM  (VMEAN_BYTE + 64 * 4)               // 91776 B

#define KS2 0.1803368801111204f   // 0.125 * log2(e)

template<int NCOLS>
__device__ __forceinline__ void attn_chunk(
    const int r0, const int g, const int tig,
    const __nv_bfloat16* __restrict__ Khs, const __nv_bfloat16* __restrict__ Kls,
    const __half* __restrict__ Vth,
    const uint32_t (&qh)[4][4], const uint32_t (&ql)[4][4],
    float (&O)[9][4], float (&m_run)[2])
{
    constexpr int NT  = NCOLS / 8;
    constexpr int KSN = NCOLS / 16;
    float S[NT][4];
    #pragma unroll
    for (int nt = 0; nt < NT; nt++)
        S[nt][0] = S[nt][1] = S[nt][2] = S[nt][3] = 0.f;

    #pragma unroll
    for (int nt = 0; nt < NT; nt++) {
        const int krow = r0 + nt * 8 + g;
        #pragma unroll
        for (int ks = 0; ks < 4; ks++) {
            const uint32_t* kh32 = (const uint32_t*)(Khs + krow * KH_STR + ks * 16 + tig * 2);
            const uint32_t* kl32 = (const uint32_t*)(Kls + krow * KH_STR + ks * 16 + tig * 2);
            uint32_t bh[2] = { kh32[0], kh32[4] };
            uint32_t bl[2] = { kl32[0], kl32[4] };
            mma16816(S[nt], qh[ks], bh);
            mma16816(S[nt], qh[ks], bl);
            mma16816(S[nt], ql[ks], bh);
        }
    }
    if (NCOLS == 16) {
        #pragma unroll
        for (int nt = 0; nt < NT; nt++) {
            int col0 = r0 + nt * 8 + tig * 2;
            if (col0 >= NN)     { S[nt][0] = -1e30f; S[nt][2] = -1e30f; }
            if (col0 + 1 >= NN) { S[nt][1] = -1e30f; S[nt][3] = -1e30f; }
        }
    }
    float cm0 = -1e30f, cm1 = -1e30f;
    #pragma unroll
    for (int nt = 0; nt < NT; nt++) {
        cm0 = fmaxf(cm0, fmaxf(S[nt][0], S[nt][1]));
        cm1 = fmaxf(cm1, fmaxf(S[nt][2], S[nt][3]));
    }
    cm0 = fmaxf(cm0, __shfl_xor_sync(0xffffffffu, cm0, 1));
    cm0 = fmaxf(cm0, __shfl_xor_sync(0xffffffffu, cm0, 2));
    cm1 = fmaxf(cm1, __shfl_xor_sync(0xffffffffu, cm1, 1));
    cm1 = fmaxf(cm1, __shfl_xor_sync(0xffffffffu, cm1, 2));

    float mn0 = fmaxf(m_run[0], cm0);
    float mn1 = fmaxf(m_run[1], cm1);
    float a0 = exp2_f32((m_run[0] - mn0) * KS2);
    float a1 = exp2_f32((m_run[1] - mn1) * KS2);
    m_run[0] = mn0; m_run[1] = mn1;
    #pragma unroll
    for (int n2 = 0; n2 < 9; n2++) {
        O[n2][0] *= a0; O[n2][1] *= a0;
        O[n2][2] *= a1; O[n2][3] *= a1;
    }
    const float mk0 = mn0 * KS2, mk1 = mn1 * KS2;
    uint32_t P[NT][2];
    #pragma unroll
    for (int nt = 0; nt < NT; nt++) {
        float t0 = fmaf(S[nt][0], KS2, -mk0);
        float t1 = fmaf(S[nt][1], KS2, -mk0);
        float t2 = fmaf(S[nt][2], KS2, -mk1);
        float t3 = fmaf(S[nt][3], KS2, -mk1);
        P[nt][0] = exp2_f16x2(t0, t1);
        P[nt][1] = exp2_f16x2(t2, t3);
    }
    #pragma unroll
    for (int ks = 0; ks < KSN; ks++) {
        uint32_t A[4] = { P[2*ks][0], P[2*ks][1], P[2*ks+1][0], P[2*ks+1][1] };
        const int kr = r0 + ks * 16 + tig * 2;
        #pragma unroll
        for (int n2 = 0; n2 < 9; n2++) {
            const uint32_t* vh32 = (const uint32_t*)(Vth + (n2 * 8 + g) * VT_STR + kr);
            uint32_t bvh[2] = { vh32[0], vh32[4] };
            mma16816h(O[n2], A, bvh);
        }
    }
}

__global__ __launch_bounds__(AT_THREADS, 2) void attn_hmma(
    const __nv_bfloat16* __restrict__ qkvh, const __nv_bfloat16* __restrict__ qkvl,
    __nv_bfloat16* __restrict__ yh, __nv_bfloat16* __restrict__ yl)
{
    extern __shared__ char smraw[];
    __nv_bfloat16* Khs = (__nv_bfloat16*)smraw;
    __nv_bfloat16* Kls = Khs + SM_KL_U;
    __half*        Vth = (__half*)(smraw + VTH_BYTE);
    float*       vpart = (float*)(smraw + VPART_BYTE);
    float*       vmean = (float*)(smraw + VMEAN_BYTE);

    const int bid = blockIdx.x;
    const int b = bid / (HH * TT);
    const int h = (bid / TT) % HH;
    const int t = bid % TT;
    const size_t row0 = (size_t)b * TNTOK + (size_t)t * NN;

    const __nv_bfloat16* qbh = qkvh + row0 * QKVCOLS + 0 * DD + h * HD;
    const __nv_bfloat16* qbl = qkvl + row0 * QKVCOLS + 0 * DD + h * HD;
    const __nv_bfloat16* kbh = qkvh + row0 * QKVCOLS + 1 * DD + h * HD;
    const __nv_bfloat16* kbl = qkvl + row0 * QKVCOLS + 1 * DD + h * HD;
    const __nv_bfloat16* vbh = qkvh + row0 * QKVCOLS + 2 * DD + h * HD;
    const __nv_bfloat16* vbl = qkvl + row0 * QKVCOLS + 2 * DD + h * HD;

    const int tid  = threadIdx.x;
    const int lane = tid & 31;
    const int w    = tid >> 5;
    const int g    = lane >> 2;
    const int tig  = lane & 3;

    // K staging: raw uint4 copies (8 bf16 per chunk, 8 chunks per 64-col row)
    for (int idx = tid; idx < NN * 8; idx += AT_THREADS) {
        int row = idx >> 3, c = idx & 7;
        *(uint4*)(Khs + row * KH_STR + c * 8) =
            *(const uint4*)(kbh + (size_t)row * QKVCOLS + c * 8);
        *(uint4*)(Kls + row * KH_STR + c * 8) =
            *(const uint4*)(kbl + (size_t)row * QKVCOLS + c * 8);
    }
    // V: f16(hi+lo), transposed [dim][row]
    for (int idx = tid; idx < NN * HD; idx += AT_THREADS) {
        int row = idx >> 6, dim = idx & 63;
        float v = __bfloat162float(vbh[(size_t)row * QKVCOLS + dim])
                + __bfloat162float(vbl[(size_t)row * QKVCOLS + dim]);
        Vth[dim * VT_STR + row] = __float2half(v);
    }
    // K pad rows 196..207
    for (int idx = tid; idx < 12 * 8; idx += AT_THREADS) {
        int row = NN + (idx >> 3), c = idx & 7;
        *(uint4*)(Khs + row * KH_STR + c * 8) = {0u, 0u, 0u, 0u};
        *(uint4*)(Kls + row * KH_STR + c * 8) = {0u, 0u, 0u, 0u};
    }
    // V pad rows 196..207 for dims 0..63
    for (int idx = tid; idx < 64 * 12; idx += AT_THREADS) {
        int dim = idx / 12, r = NN + (idx % 12);
        Vth[dim * VT_STR + r] = __ushort_as_half(0);
    }
    // dims 64..71: ones column (dim 64) else zeros
    for (int idx = tid; idx < 8 * AT_KPAD; idx += AT_THREADS) {
        int dim = 64 + idx / AT_KPAD, r = idx % AT_KPAD;
        Vth[dim * VT_STR + r] = (dim == 64) ? __float2half(1.0f) : __ushort_as_half(0);
    }
    __syncthreads();
    // vmean: 128 threads, 2 partials of 98 rows per dim
    if (tid < 128) {
        int part = tid >> 6, dim = tid & 63;
        int rlo = part * 98, rhi = rlo + 98;
        float s = 0.f;
        const __half* vh = Vth + dim * VT_STR;
        for (int r = rlo; r < rhi; r++) s += __half2float(vh[r]);
        vpart[part * 64 + dim] = s;
    }
    __syncthreads();
    if (tid < 64)
        vmean[tid] = (vpart[tid] + vpart[64 + tid]) * (1.0f / NN);
    __syncthreads();

    #pragma unroll 1
    for (int mt = 0; mt < 2; mt++) {
        int ra = w * 32 + mt * 16 + g;
        int rb = ra + 8;
        int rac = (ra > 195) ? 195 : ra;
        int rbc = (rb > 195) ? 195 : rb;

        // Q fragments: direct u32 loads of pre-split hi/lo bf16
        uint32_t qh[4][4], ql[4][4];
        #pragma unroll
        for (int ks = 0; ks < 4; ks++) {
            #pragma unroll
            for (int hf = 0; hf < 2; hf++) {
                int k = ks * 16 + tig * 2 + hf * 8;
                qh[ks][hf * 2 + 0] = *(const uint32_t*)(qbh + (size_t)rac * QKVCOLS + k);
                qh[ks][hf * 2 + 1] = *(const uint32_t*)(qbh + (size_t)rbc * QKVCOLS + k);
                ql[ks][hf * 2 + 0] = *(const uint32_t*)(qbl + (size_t)rac * QKVCOLS + k);
                ql[ks][hf * 2 + 1] = *(const uint32_t*)(qbl + (size_t)rbc * QKVCOLS + k);
            }
        }

        float O[9][4];
        #pragma unroll
        for (int n2 = 0; n2 < 9; n2++)
            O[n2][0] = O[n2][1] = O[n2][2] = O[n2][3] = 0.f;
        float m_run[2] = { -1e30f, -1e30f };

        attn_chunk<64>(  0, g, tig, Khs, Kls, Vth, qh, ql, O, m_run);
        attn_chunk<64>( 64, g, tig, Khs, Kls, Vth, qh, ql, O, m_run);
        attn_chunk<64>(128, g, tig, Khs, Kls, Vth, qh, ql, O, m_run);
        attn_chunk<16>(192, g, tig, Khs, Kls, Vth, qh, ql, O, m_run);

        float l0 = __shfl_sync(0xffffffffu, O[8][0], lane & ~3);
        float l1 = __shfl_sync(0xffffffffu, O[8][2], lane & ~3);
        float inv0 = 1.0f / l0, inv1 = 1.0f / l1;
        #pragma unroll
        for (int n2 = 0; n2 < 8; n2++) {
            int dim = n2 * 8 + tig * 2;
            float vm0 = vmean[dim], vm1 = vmean[dim + 1];
            if (ra < NN) {
                float v0 = fmaf(O[n2][0], inv0, vm0);
                float v1 = fmaf(O[n2][1], inv0, vm1);
                __nv_bfloat16 hh0 = __float2bfloat16(v0), hh1 = __float2bfloat16(v1);
                size_t ob = (row0 + ra) * DD + h * HD + dim;
                *(uint32_t*)(yh + ob) = pack_bf16x2(v0, v1);
                *(uint32_t*)(yl + ob) = pack_bf16x2(v0 - __bfloat162float(hh0),
                                                    v1 - __bfloat162float(hh1));
            }
            if (rb < NN) {
                float v0 = fmaf(O[n2][2], inv1, vm0);
                float v1 = fmaf(O[n2][3], inv1, vm1);
                __nv_bfloat16 hh0 = __float2bfloat16(v0), hh1 = __float2bfloat16(v1);
                size_t ob = (row0 + rb) * DD + h * HD + dim;
                *(uint32_t*)(yh + ob) = pack_bf16x2(v0, v1);
                *(uint32_t*)(yl + ob) = pack_bf16x2(v0 - __bfloat162float(hh0),
                                                    v1 - __bfloat162float(hh1));
            }
        }
    }
}

// ---------------- launch --------------------------------------------------
extern "C" void kernel_launch(void* const* d_in, const int* in_sizes, int n_in,
                              void* d_out, int out_size)
{
    const float* x = nullptr;
    const float* w_qkv = nullptr;
    const float* w_proj = nullptr;
    const float* b_proj = nullptr;
    for (int i = 0; i < n_in; i++) {
        long sz = in_sizes[i];
        if      (sz == (long)MROWS * DD)   { if (!x) x = (const float*)d_in[i]; }
        else if (sz == (long)DD * QKVCOLS) w_qkv  = (const float*)d_in[i];
        else if (sz == (long)DD * DD)      w_proj = (const float*)d_in[i];
        else if (sz == (long)DD)           b_proj = (const float*)d_in[i];
    }

    void *xh, *xl, *wqh, *wql, *wph, *wpl, *qkvh, *qkvl, *yh, *yl;
    cudaGetSymbolAddress(&xh, g_xh);   cudaGetSymbolAddress(&xl, g_xl);
    cudaGetSymbolAddress(&wqh, g_wqkvT_h); cudaGetSymbolAddress(&wql, g_wqkvT_l);
    cudaGetSymbolAddress(&wph, g_wprojT_h); cudaGetSymbolAddress(&wpl, g_wprojT_l);
    cudaGetSymbolAddress(&qkvh, g_qkvh); cudaGetSymbolAddress(&qkvl, g_qkvl);
    cudaGetSymbolAddress(&yh, g_yh);   cudaGetSymbolAddress(&yl, g_yl);

    {
        int n4 = MROWS * DD / 4;
        convert_split<<<(n4 + 255) / 256, 256>>>(x, (__nv_bfloat16*)xh, (__nv_bfloat16*)xl, n4);
        transpose_split<<<dim3(QKVCOLS / 32, DD / 32), dim3(32, 8)>>>(
            w_qkv, (__nv_bfloat16*)wqh, (__nv_bfloat16*)wql, DD, QKVCOLS);
        transpose_split<<<dim3(DD / 32, DD / 32), dim3(32, 8)>>>(
            w_proj, (__nv_bfloat16*)wph, (__nv_bfloat16*)wpl, DD, DD);
    }

    cudaFuncSetAttribute(gemm_split_hmma, cudaFuncAttributeMaxDynamicSharedMemorySize, G_SMEM);
    cudaFuncSetAttribute(attn_hmma, cudaFuncAttributeMaxDynamicSharedMemorySize, AT_SMEM);

    // 1) QKV projection -> split hi/lo bf16 output
    gemm_split_hmma<<<dim3(QKVCOLS / 128, MROWS / 128), 128, G_SMEM>>>(
        (const __nv_bfloat16*)xh, (const __nv_bfloat16*)xl,
        (const __nv_bfloat16*)wqh, (const __nv_bfloat16*)wql,
        nullptr, nullptr, (__nv_bfloat16*)qkvh, (__nv_bfloat16*)qkvl, QKVCOLS, DD);

    // 2) HMMA attention (per-frame, 2 CTA/SM), consumes split qkv directly
    attn_hmma<<<BB * HH * TT, AT_THREADS, AT_SMEM>>>(
        (const __nv_bfloat16*)qkvh, (const __nv_bfloat16*)qkvl,
        (__nv_bfloat16*)yh, (__nv_bfloat16*)yl);

    // 3) output projection + bias (f32 out)
    gemm_split_hmma<<<dim3(DD / 128, MROWS / 128), 128, G_SMEM>>>(
        (const __nv_bfloat16*)yh, (const __nv_bfloat16*)yl,
        (const __nv_bfloat16*)wph, (const __nv_bfloat16*)wpl,
        b_proj, (float*)d_out, nullptr, nullptr, DD, DD);
}

// round 16
// speedup vs baseline: 1.3008x; 1.3008x over previous
#include <cuda_runtime.h>
#include <cuda_bf16.h>
#include <cuda_fp16.h>
#include <cstdint>
#include <cstddef>

// ---------------- problem constants ----------------
#define BB      8
#define TT      8
#define NN      196
#define DD      768
#define HH      12
#define HD      64
#define TNTOK   (TT*NN)            // 1568
#define MROWS   (BB*TNTOK)         // 12544
#define QKVCOLS (3*DD)             // 2304

// ---------------- scratch ----------------
__device__ __half g_xh16[(size_t)MROWS * DD];
__device__ __half g_xl16[(size_t)MROWS * DD];
__device__ __half g_wqkvT16[(size_t)QKVCOLS * DD];
__device__ __half g_wprojT16[(size_t)DD * DD];
__device__ float  g_qkv[(size_t)MROWS * QKVCOLS];
__device__ __half g_yh16[(size_t)MROWS * DD];
__device__ __half g_yl16[(size_t)MROWS * DD];

// ---------------- helpers ----------------
__device__ __forceinline__ uint32_t smem_u32(const void* p) {
    uint32_t a;
    asm("{ .reg .u64 t; cvta.to.shared.u64 t, %1; cvt.u32.u64 %0, t; }" : "=r"(a) : "l"(p));
    return a;
}
__device__ __forceinline__ void mma16816(float* c, const uint32_t* a, const uint32_t* b) {
    asm volatile(
        "mma.sync.aligned.m16n8k16.row.col.f32.bf16.bf16.f32 "
        "{%0,%1,%2,%3}, {%4,%5,%6,%7}, {%8,%9}, {%0,%1,%2,%3};"
        : "+f"(c[0]), "+f"(c[1]), "+f"(c[2]), "+f"(c[3])
        : "r"(a[0]), "r"(a[1]), "r"(a[2]), "r"(a[3]), "r"(b[0]), "r"(b[1]));
}
__device__ __forceinline__ void mma16816h(float* c, const uint32_t* a, const uint32_t* b) {
    asm volatile(
        "mma.sync.aligned.m16n8k16.row.col.f32.f16.f16.f32 "
        "{%0,%1,%2,%3}, {%4,%5,%6,%7}, {%8,%9}, {%0,%1,%2,%3};"
        : "+f"(c[0]), "+f"(c[1]), "+f"(c[2]), "+f"(c[3])
        : "r"(a[0]), "r"(a[1]), "r"(a[2]), "r"(a[3]), "r"(b[0]), "r"(b[1]));
}
__device__ __forceinline__ void ldsm4(uint32_t& r0, uint32_t& r1, uint32_t& r2, uint32_t& r3,
                                      uint32_t addr) {
    asm volatile("ldmatrix.sync.aligned.m8n8.x4.shared.b16 {%0,%1,%2,%3}, [%4];"
        : "=r"(r0), "=r"(r1), "=r"(r2), "=r"(r3) : "r"(addr));
}
#define CP_ASYNC16(dst, src) \
    asm volatile("cp.async.cg.shared.global [%0], [%1], 16;" :: "r"(dst), "l"(src))
#define CP_COMMIT() asm volatile("cp.async.commit_group;" ::: "memory")

__device__ __forceinline__ uint32_t pack_bf16x2(float lo, float hi) {
    uint32_t d;
    asm("cvt.rn.bf16x2.f32 %0, %1, %2;" : "=r"(d) : "f"(hi), "f"(lo));
    return d;
}
__device__ __forceinline__ uint32_t pack_f16x2(float lo, float hi) {
    uint32_t d;
    asm("cvt.rn.f16x2.f32 %0, %1, %2;" : "=r"(d) : "f"(hi), "f"(lo));
    return d;
}
__device__ __forceinline__ uint32_t exp2_f16x2(float lo, float hi) {
    uint32_t t, d;
    asm("cvt.rn.f16x2.f32 %0, %1, %2;" : "=r"(t) : "f"(hi), "f"(lo));
    asm("ex2.approx.f16x2 %0, %1;" : "=r"(d) : "r"(t));
    return d;
}
__device__ __forceinline__ float exp2_f32(float x) {
    float d;
    asm("ex2.approx.f32 %0, %1;" : "=f"(d) : "f"(x));
    return d;
}

// ---------------- prep: fp32 -> f16 hi/lo split (elementwise) ---------------
__global__ __launch_bounds__(256) void convert_split_f16(
    const float* __restrict__ src, __half* __restrict__ dh,
    __half* __restrict__ dl, int n4)
{
    int i = blockIdx.x * blockDim.x + threadIdx.x;
    if (i >= n4) return;
    float4 v = *(const float4*)(src + (size_t)i * 4);
    __half h0 = __float2half(v.x), h1 = __float2half(v.y);
    __half h2 = __float2half(v.z), h3 = __float2half(v.w);
    *(uint32_t*)(dh + (size_t)i * 4 + 0) = pack_f16x2(v.x, v.y);
    *(uint32_t*)(dh + (size_t)i * 4 + 2) = pack_f16x2(v.z, v.w);
    *(uint32_t*)(dl + (size_t)i * 4 + 0) =
        pack_f16x2(v.x - __half2float(h0), v.y - __half2float(h1));
    *(uint32_t*)(dl + (size_t)i * 4 + 2) =
        pack_f16x2(v.z - __half2float(h2), v.w - __half2float(h3));
}

// ---------------- prep: transpose weights [K][N] -> [N][K] f16 --------------
__global__ __launch_bounds__(256) void transpose_f16(
    const float* __restrict__ src, __half* __restrict__ dh, int K, int N)
{
    __shared__ float t[32][33];
    int n0 = blockIdx.x * 32, k0 = blockIdx.y * 32;
    int tx = threadIdx.x, ty = threadIdx.y;   // block (32, 8)
    #pragma unroll
    for (int j = ty; j < 32; j += 8)
        t[j][tx] = src[(size_t)(k0 + j) * N + n0 + tx];
    __syncthreads();
    #pragma unroll
    for (int j = ty; j < 32; j += 8)
        dh[(size_t)(n0 + j) * K + k0 + tx] = __float2half(t[tx][j]);
}

// ---------------- 2-term f16 HMMA GEMM: C = (Ah+Al) * Bh^T [+bias] ----------
// A split f16 hi/lo (exact to ~1e-7); B single f16 (error 2.8e-4 RMS).
// 128x128 tile, 4 warps 64x64, 2 MMAs/acc per ks (was 3), stage = 3 tiles.
#define G_BK        32
#define G_ROWB      80
#define G_TILE_B    (128 * G_ROWB)          // 10240 B
#define G_STAGE_B   (3 * G_TILE_B)          // 30720 B
#define G_SMEM      (2 * G_STAGE_B)         // 61440 B

__global__ __launch_bounds__(128, 2) void gemm_f16_2t(
    const __half* __restrict__ Ah, const __half* __restrict__ Al,
    const __half* __restrict__ Bh,
    const float* __restrict__ bias, float* __restrict__ C, int Ncols, int K)
{
    extern __shared__ char sm[];
    const int tid  = threadIdx.x;
    const int lane = tid & 31;
    const int wid  = tid >> 5;
    const int warp_m = wid >> 1;
    const int warp_n = wid & 1;
    const int g   = lane >> 2;
    const int tig = lane & 3;

    const size_t arow0 = (size_t)blockIdx.y * 128;
    const size_t brow0 = (size_t)blockIdx.x * 128;

    const __half* gA[3] = { Ah + arow0 * K, Al + arow0 * K, Bh + brow0 * K };

    // stage copy: 3 tiles x 128 rows x 4 chunks(16B) = 1536 chunks, 12/thread
    const int lrow = tid >> 2;        // 0..31
    const int c16  = tid & 3;
    auto load_stage = [&](int s, int k0) {
        char* base = sm + s * G_STAGE_B;
        #pragma unroll
        for (int i = 0; i < 12; i++) {
            const int t   = i >> 2;
            const int row = (i & 3) * 32 + lrow;
            const __half* src = gA[t] + (size_t)row * K + k0 + c16 * 8;
            uint32_t dst = smem_u32(base + t * G_TILE_B + row * G_ROWB + c16 * 16);
            CP_ASYNC16(dst, src);
        }
        CP_COMMIT();
    };

    const uint32_t aoff = (uint32_t)((warp_m * 64 + (lane & 15)) * G_ROWB
                                     + (lane >> 4) * 16);
    const uint32_t boff = (uint32_t)((warp_n * 64 + ((lane >> 4) << 3) + (lane & 7)) * G_ROWB
                                     + ((lane >> 3) & 1) * 16);
    const uint32_t smbu = smem_u32(sm);

    float acc[4][8][4];
    #pragma unroll
    for (int mt = 0; mt < 4; mt++)
        #pragma unroll
        for (int nt = 0; nt < 8; nt++)
            #pragma unroll
            for (int i = 0; i < 4; i++) acc[mt][nt][i] = 0.f;

    load_stage(0, 0);

    const int KT = K / G_BK;
    for (int kt = 0; kt < KT; kt++) {
        if (kt + 1 < KT) {
            load_stage((kt + 1) & 1, (kt + 1) * G_BK);
            asm volatile("cp.async.wait_group 1;" ::: "memory");
        } else {
            asm volatile("cp.async.wait_group 0;" ::: "memory");
        }
        __syncthreads();

        const uint32_t sbu  = smbu + (kt & 1) * G_STAGE_B;
        const uint32_t sAhU = sbu + 0 * G_TILE_B + aoff;
        const uint32_t sAlU = sbu + 1 * G_TILE_B + aoff;
        const uint32_t sBhU = sbu + 2 * G_TILE_B + boff;

        #pragma unroll
        for (int ks = 0; ks < 2; ks++) {
            const uint32_t ksb = (uint32_t)(ks * 32);
            uint32_t ah[4][4], al[4][4], bh[4][4];
            #pragma unroll
            for (int np = 0; np < 4; np++)
                ldsm4(bh[np][0], bh[np][1], bh[np][2], bh[np][3],
                      sBhU + np * (16 * G_ROWB) + ksb);
            #pragma unroll
            for (int mt = 0; mt < 4; mt++) {
                ldsm4(ah[mt][0], ah[mt][1], ah[mt][2], ah[mt][3],
                      sAhU + mt * (16 * G_ROWB) + ksb);
                ldsm4(al[mt][0], al[mt][1], al[mt][2], al[mt][3],
                      sAlU + mt * (16 * G_ROWB) + ksb);
            }
            #pragma unroll
            for (int mt = 0; mt < 4; mt++) {
                #pragma unroll
                for (int np = 0; np < 4; np++) {
                    mma16816h(acc[mt][2 * np + 0], ah[mt], &bh[np][0]);
                    mma16816h(acc[mt][2 * np + 1], ah[mt], &bh[np][2]);
                }
                #pragma unroll
                for (int np = 0; np < 4; np++) {
                    mma16816h(acc[mt][2 * np + 0], al[mt], &bh[np][0]);
                    mma16816h(acc[mt][2 * np + 1], al[mt], &bh[np][2]);
                }
            }
        }
        __syncthreads();
    }

    const size_t col0 = (size_t)blockIdx.x * 128 + warp_n * 64;
    #pragma unroll
    for (int mt = 0; mt < 4; mt++) {
        size_t row = arow0 + warp_m * 64 + mt * 16 + g;
        #pragma unroll
        for (int nt = 0; nt < 8; nt++) {
            size_t col = col0 + nt * 8 + tig * 2;
            float b0 = 0.f, b1 = 0.f;
            if (bias) { b0 = bias[col]; b1 = bias[col + 1]; }
            float2 v0 = { acc[mt][nt][0] + b0, acc[mt][nt][1] + b1 };
            float2 v1 = { acc[mt][nt][2] + b0, acc[mt][nt][3] + b1 };
            *(float2*)(C + row * Ncols + col)       = v0;
            *(float2*)(C + (row + 8) * Ncols + col) = v1;
        }
    }
}

// ---------------- HMMA attention (round-14 proven; y out as f16 hi/lo) ------
#define AT_THREADS 448
#define KH_STR   72            // K hi/lo row stride (bf16 units)
#define VT_STR   216           // V^T row stride (f16 units)
#define AT_KPAD  208
#define SM_KL_U  (AT_KPAD * KH_STR)
#define VTH_BYTE (2 * 2 * AT_KPAD * KH_STR)          // 59904
#define VPART_BYTE (VTH_BYTE + 2 * 72 * VT_STR)      // +31104 = 91008
#define VMEAN_BYTE (VPART_BYTE + 4 * 64 * 4)         // +1024
#define AT_SMEM  (VMEAN_BYTE + 64 * 4)               // 92288 B

#define KS2 0.1803368801111204f   // 0.125 * log2(e)

template<int NCOLS>
__device__ __forceinline__ void attn_chunk(
    const int r0, const int g, const int tig,
    const __nv_bfloat16* __restrict__ Khs, const __nv_bfloat16* __restrict__ Kls,
    const __half* __restrict__ Vth,
    const uint32_t (&qh)[4][4], const uint32_t (&ql)[4][4],
    float (&O)[9][4], float (&m_run)[2])
{
    constexpr int NT  = NCOLS / 8;
    constexpr int KSN = NCOLS / 16;
    float S[NT][4];
    #pragma unroll
    for (int nt = 0; nt < NT; nt++)
        S[nt][0] = S[nt][1] = S[nt][2] = S[nt][3] = 0.f;

    #pragma unroll
    for (int nt = 0; nt < NT; nt++) {
        const int krow = r0 + nt * 8 + g;
        #pragma unroll
        for (int ks = 0; ks < 4; ks++) {
            const uint32_t* kh32 = (const uint32_t*)(Khs + krow * KH_STR + ks * 16 + tig * 2);
            const uint32_t* kl32 = (const uint32_t*)(Kls + krow * KH_STR + ks * 16 + tig * 2);
            uint32_t bh[2] = { kh32[0], kh32[4] };
            uint32_t bl[2] = { kl32[0], kl32[4] };
            mma16816(S[nt], qh[ks], bh);
            mma16816(S[nt], qh[ks], bl);
            mma16816(S[nt], ql[ks], bh);
        }
    }
    if (NCOLS == 16) {
        #pragma unroll
        for (int nt = 0; nt < NT; nt++) {
            int col0 = r0 + nt * 8 + tig * 2;
            if (col0 >= NN)     { S[nt][0] = -1e30f; S[nt][2] = -1e30f; }
            if (col0 + 1 >= NN) { S[nt][1] = -1e30f; S[nt][3] = -1e30f; }
        }
    }
    float cm0 = -1e30f, cm1 = -1e30f;
    #pragma unroll
    for (int nt = 0; nt < NT; nt++) {
        cm0 = fmaxf(cm0, fmaxf(S[nt][0], S[nt][1]));
        cm1 = fmaxf(cm1, fmaxf(S[nt][2], S[nt][3]));
    }
    cm0 = fmaxf(cm0, __shfl_xor_sync(0xffffffffu, cm0, 1));
    cm0 = fmaxf(cm0, __shfl_xor_sync(0xffffffffu, cm0, 2));
    cm1 = fmaxf(cm1, __shfl_xor_sync(0xffffffffu, cm1, 1));
    cm1 = fmaxf(cm1, __shfl_xor_sync(0xffffffffu, cm1, 2));

    float mn0 = fmaxf(m_run[0], cm0);
    float mn1 = fmaxf(m_run[1], cm1);
    float a0 = exp2_f32((m_run[0] - mn0) * KS2);
    float a1 = exp2_f32((m_run[1] - mn1) * KS2);
    m_run[0] = mn0; m_run[1] = mn1;
    #pragma unroll
    for (int n2 = 0; n2 < 9; n2++) {
        O[n2][0] *= a0; O[n2][1] *= a0;
        O[n2][2] *= a1; O[n2][3] *= a1;
    }
    const float mk0 = mn0 * KS2, mk1 = mn1 * KS2;
    uint32_t P[NT][2];
    #pragma unroll
    for (int nt = 0; nt < NT; nt++) {
        float t0 = fmaf(S[nt][0], KS2, -mk0);
        float t1 = fmaf(S[nt][1], KS2, -mk0);
        float t2 = fmaf(S[nt][2], KS2, -mk1);
        float t3 = fmaf(S[nt][3], KS2, -mk1);
        P[nt][0] = exp2_f16x2(t0, t1);
        P[nt][1] = exp2_f16x2(t2, t3);
    }
    #pragma unroll
    for (int ks = 0; ks < KSN; ks++) {
        uint32_t A[4] = { P[2*ks][0], P[2*ks][1], P[2*ks+1][0], P[2*ks+1][1] };
        const int kr = r0 + ks * 16 + tig * 2;
        #pragma unroll
        for (int n2 = 0; n2 < 9; n2++) {
            const uint32_t* vh32 = (const uint32_t*)(Vth + (n2 * 8 + g) * VT_STR + kr);
            uint32_t bvh[2] = { vh32[0], vh32[4] };
            mma16816h(O[n2], A, bvh);
        }
    }
}

__global__ __launch_bounds__(AT_THREADS) void attn_hmma(
    const float* __restrict__ qkv,
    __half* __restrict__ yh, __half* __restrict__ yl)
{
    extern __shared__ char smraw[];
    __nv_bfloat16* Khs = (__nv_bfloat16*)smraw;
    __nv_bfloat16* Kls = Khs + SM_KL_U;
    __half*        Vth = (__half*)(smraw + VTH_BYTE);
    float*       vpart = (float*)(smraw + VPART_BYTE);
    float*       vmean = (float*)(smraw + VMEAN_BYTE);

    const int bid = blockIdx.x;
    const int b = bid / (HH * TT);
    const int h = (bid / TT) % HH;
    const int t = bid % TT;
    const size_t row0 = (size_t)b * TNTOK + (size_t)t * NN;

    const float* qbase = qkv + row0 * QKVCOLS + 0 * DD + h * HD;
    const float* kbase = qkv + row0 * QKVCOLS + 1 * DD + h * HD;
    const float* vbase = qkv + row0 * QKVCOLS + 2 * DD + h * HD;

    const int tid  = threadIdx.x;
    const int lane = tid & 31;
    const int w    = tid >> 5;        // 0..13, warp w owns rows [16w, 16w+16)
    const int g    = lane >> 2;
    const int tig  = lane & 3;

    for (int idx = tid; idx < NN * 16; idx += AT_THREADS) {
        int row = idx >> 4, d4 = (idx & 15) * 4;
        float4 v = *(const float4*)(kbase + (size_t)row * QKVCOLS + d4);
        __nv_bfloat16 h0 = __float2bfloat16(v.x), h1 = __float2bfloat16(v.y);
        __nv_bfloat16 h2 = __float2bfloat16(v.z), h3 = __float2bfloat16(v.w);
        __nv_bfloat162* ph = (__nv_bfloat162*)(Khs + row * KH_STR + d4);
        __nv_bfloat162* pl = (__nv_bfloat162*)(Kls + row * KH_STR + d4);
        ph[0] = {h0, h1}; ph[1] = {h2, h3};
        pl[0] = {__float2bfloat16(v.x - __bfloat162float(h0)),
                 __float2bfloat16(v.y - __bfloat162float(h1))};
        pl[1] = {__float2bfloat16(v.z - __bfloat162float(h2)),
                 __float2bfloat16(v.w - __bfloat162float(h3))};
    }
    for (int idx = tid; idx < NN * HD; idx += AT_THREADS) {
        int row = idx >> 6, dim = idx & 63;
        Vth[dim * VT_STR + row] = __float2half(vbase[(size_t)row * QKVCOLS + dim]);
    }
    for (int idx = tid; idx < 12 * 16; idx += AT_THREADS) {
        int row = NN + (idx >> 4), d4 = (idx & 15) * 4;
        *(uint2*)(Khs + row * KH_STR + d4) = {0u, 0u};
        *(uint2*)(Kls + row * KH_STR + d4) = {0u, 0u};
    }
    for (int idx = tid; idx < 64 * 12; idx += AT_THREADS) {
        int dim = idx / 12, r = NN + (idx % 12);
        Vth[dim * VT_STR + r] = __ushort_as_half(0);
    }
    for (int idx = tid; idx < 8 * AT_KPAD; idx += AT_THREADS) {
        int dim = 64 + idx / AT_KPAD, r = idx % AT_KPAD;
        Vth[dim * VT_STR + r] = (dim == 64) ? __float2half(1.0f) : __ushort_as_half(0);
    }
    __syncthreads();
    if (tid < 256) {
        int part = tid >> 6, dim = tid & 63;
        int rlo = part * 49, rhi = rlo + 49;
        float s = 0.f;
        const __half* vh = Vth + dim * VT_STR;
        for (int r = rlo; r < rhi; r++) s += __half2float(vh[r]);
        vpart[part * 64 + dim] = s;
    }
    __syncthreads();
    if (tid < 64) {
        vmean[tid] = (vpart[tid] + vpart[64 + tid] + vpart[128 + tid] + vpart[192 + tid])
                     * (1.0f / NN);
    }
    __syncthreads();

    int ra = w * 16 + g;
    int rb = ra + 8;
    int rac = (ra > 195) ? 195 : ra;
    int rbc = (rb > 195) ? 195 : rb;

    uint32_t qh[4][4], ql[4][4];
    #pragma unroll
    for (int ks = 0; ks < 4; ks++) {
        #pragma unroll
        for (int hf = 0; hf < 2; hf++) {
            int k = ks * 16 + tig * 2 + hf * 8;
            float2 va = *(const float2*)(qbase + (size_t)rac * QKVCOLS + k);
            float2 vb = *(const float2*)(qbase + (size_t)rbc * QKVCOLS + k);
            __nv_bfloat16 ha0 = __float2bfloat16(va.x), ha1 = __float2bfloat16(va.y);
            __nv_bfloat16 hb0 = __float2bfloat16(vb.x), hb1 = __float2bfloat16(vb.y);
            qh[ks][hf * 2 + 0] = pack_bf16x2(va.x, va.y);
            qh[ks][hf * 2 + 1] = pack_bf16x2(vb.x, vb.y);
            ql[ks][hf * 2 + 0] =
                pack_bf16x2(va.x - __bfloat162float(ha0), va.y - __bfloat162float(ha1));
            ql[ks][hf * 2 + 1] =
                pack_bf16x2(vb.x - __bfloat162float(hb0), vb.y - __bfloat162float(hb1));
        }
    }

    float O[9][4];
    #pragma unroll
    for (int n2 = 0; n2 < 9; n2++)
        O[n2][0] = O[n2][1] = O[n2][2] = O[n2][3] = 0.f;
    float m_run[2] = { -1e30f, -1e30f };

    attn_chunk<64>(  0, g, tig, Khs, Kls, Vth, qh, ql, O, m_run);
    attn_chunk<64>( 64, g, tig, Khs, Kls, Vth, qh, ql, O, m_run);
    attn_chunk<64>(128, g, tig, Khs, Kls, Vth, qh, ql, O, m_run);
    attn_chunk<16>(192, g, tig, Khs, Kls, Vth, qh, ql, O, m_run);

    float l0 = __shfl_sync(0xffffffffu, O[8][0], lane & ~3);
    float l1 = __shfl_sync(0xffffffffu, O[8][2], lane & ~3);
    float inv0 = 1.0f / l0, inv1 = 1.0f / l1;
    #pragma unroll
    for (int n2 = 0; n2 < 8; n2++) {
        int dim = n2 * 8 + tig * 2;
        float vm0 = vmean[dim], vm1 = vmean[dim + 1];
        if (ra < NN) {
            float v0 = fmaf(O[n2][0], inv0, vm0);
            float v1 = fmaf(O[n2][1], inv0, vm1);
            __half h0 = __float2half(v0), h1 = __float2half(v1);
            size_t ob = (row0 + ra) * DD + h * HD + dim;
            *(uint32_t*)(yh + ob) = pack_f16x2(v0, v1);
            *(uint32_t*)(yl + ob) = pack_f16x2(v0 - __half2float(h0),
                                               v1 - __half2float(h1));
        }
        if (rb < NN) {
            float v0 = fmaf(O[n2][2], inv1, vm0);
            float v1 = fmaf(O[n2][3], inv1, vm1);
            __half h0 = __float2half(v0), h1 = __float2half(v1);
            size_t ob = (row0 + rb) * DD + h * HD + dim;
            *(uint32_t*)(yh + ob) = pack_f16x2(v0, v1);
            *(uint32_t*)(yl + ob) = pack_f16x2(v0 - __half2float(h0),
                                               v1 - __half2float(h1));
        }
    }
}

// ---------------- launch --------------------------------------------------
extern "C" void kernel_launch(void* const* d_in, const int* in_sizes, int n_in,
                              void* d_out, int out_size)
{
    const float* x = nullptr;
    const float* w_qkv = nullptr;
    const float* w_proj = nullptr;
    const float* b_proj = nullptr;
    for (int i = 0; i < n_in; i++) {
        long sz = in_sizes[i];
        if      (sz == (long)MROWS * DD)   { if (!x) x = (const float*)d_in[i]; }
        else if (sz == (long)DD * QKVCOLS) w_qkv  = (const float*)d_in[i];
        else if (sz == (long)DD * DD)      w_proj = (const float*)d_in[i];
        else if (sz == (long)DD)           b_proj = (const float*)d_in[i];
    }

    void *xh, *xl, *wq, *wp, *qkv, *yh, *yl;
    cudaGetSymbolAddress(&xh, g_xh16);  cudaGetSymbolAddress(&xl, g_xl16);
    cudaGetSymbolAddress(&wq, g_wqkvT16);
    cudaGetSymbolAddress(&wp, g_wprojT16);
    cudaGetSymbolAddress(&qkv, g_qkv);
    cudaGetSymbolAddress(&yh, g_yh16);  cudaGetSymbolAddress(&yl, g_yl16);

    {
        int n4 = MROWS * DD / 4;
        convert_split_f16<<<(n4 + 255) / 256, 256>>>(x, (__half*)xh, (__half*)xl, n4);
        transpose_f16<<<dim3(QKVCOLS / 32, DD / 32), dim3(32, 8)>>>(
            w_qkv, (__half*)wq, DD, QKVCOLS);
        transpose_f16<<<dim3(DD / 32, DD / 32), dim3(32, 8)>>>(
            w_proj, (__half*)wp, DD, DD);
    }

    cudaFuncSetAttribute(gemm_f16_2t, cudaFuncAttributeMaxDynamicSharedMemorySize, G_SMEM);
    cudaFuncSetAttribute(attn_hmma, cudaFuncAttributeMaxDynamicSharedMemorySize, AT_SMEM);

    // 1) QKV projection: (xh+xl)·w16 -> f32 qkv
    gemm_f16_2t<<<dim3(QKVCOLS / 128, MROWS / 128), 128, G_SMEM>>>(
        (const __half*)xh, (const __half*)xl, (const __half*)wq,
        nullptr, (float*)qkv, QKVCOLS, DD);

    // 2) HMMA attention (round-14 448-thr), emits f16 hi/lo y
    attn_hmma<<<BB * HH * TT, AT_THREADS, AT_SMEM>>>(
        (const float*)qkv, (__half*)yh, (__half*)yl);

    // 3) output projection + bias: (yh+yl)·wproj16 -> f32 out
    gemm_f16_2t<<<dim3(DD / 128, MROWS / 128), 128, G_SMEM>>>(
        (const __half*)yh, (const __half*)yl, (const __half*)wp,
        b_proj, (float*)d_out, DD, DD);
}

// round 17
// speedup vs baseline: 1.3436x; 1.0329x over previous
#include <cuda_runtime.h>
#include <cuda_bf16.h>
#include <cuda_fp16.h>
#include <cstdint>
#include <cstddef>

// ---------------- problem constants ----------------
#define BB      8
#define TT      8
#define NN      196
#define DD      768
#define HH      12
#define HD      64
#define TNTOK   (TT*NN)            // 1568
#define MROWS   (BB*TNTOK)         // 12544
#define QKVCOLS (3*DD)             // 2304

// ---------------- scratch ----------------
__device__ __half g_xh16[(size_t)MROWS * DD];
__device__ __half g_xl16[(size_t)MROWS * DD];
__device__ __half g_wqkvT16[(size_t)QKVCOLS * DD];
__device__ __half g_wprojT16[(size_t)DD * DD];
__device__ float  g_qkv[(size_t)MROWS * QKVCOLS];
__device__ __half g_yh16[(size_t)MROWS * DD];
__device__ __half g_yl16[(size_t)MROWS * DD];

// ---------------- helpers ----------------
__device__ __forceinline__ uint32_t smem_u32(const void* p) {
    uint32_t a;
    asm("{ .reg .u64 t; cvta.to.shared.u64 t, %1; cvt.u32.u64 %0, t; }" : "=r"(a) : "l"(p));
    return a;
}
__device__ __forceinline__ void mma16816h(float* c, const uint32_t* a, const uint32_t* b) {
    asm volatile(
        "mma.sync.aligned.m16n8k16.row.col.f32.f16.f16.f32 "
        "{%0,%1,%2,%3}, {%4,%5,%6,%7}, {%8,%9}, {%0,%1,%2,%3};"
        : "+f"(c[0]), "+f"(c[1]), "+f"(c[2]), "+f"(c[3])
        : "r"(a[0]), "r"(a[1]), "r"(a[2]), "r"(a[3]), "r"(b[0]), "r"(b[1]));
}
__device__ __forceinline__ void ldsm4(uint32_t& r0, uint32_t& r1, uint32_t& r2, uint32_t& r3,
                                      uint32_t addr) {
    asm volatile("ldmatrix.sync.aligned.m8n8.x4.shared.b16 {%0,%1,%2,%3}, [%4];"
        : "=r"(r0), "=r"(r1), "=r"(r2), "=r"(r3) : "r"(addr));
}
#define CP_ASYNC16(dst, src) \
    asm volatile("cp.async.cg.shared.global [%0], [%1], 16;" :: "r"(dst), "l"(src))
#define CP_COMMIT() asm volatile("cp.async.commit_group;" ::: "memory")

__device__ __forceinline__ uint32_t pack_f16x2(float lo, float hi) {
    uint32_t d;
    asm("cvt.rn.f16x2.f32 %0, %1, %2;" : "=r"(d) : "f"(hi), "f"(lo));
    return d;
}
__device__ __forceinline__ uint32_t exp2_f16x2(float lo, float hi) {
    uint32_t t, d;
    asm("cvt.rn.f16x2.f32 %0, %1, %2;" : "=r"(t) : "f"(hi), "f"(lo));
    asm("ex2.approx.f16x2 %0, %1;" : "=r"(d) : "r"(t));
    return d;
}
__device__ __forceinline__ float exp2_f32(float x) {
    float d;
    asm("ex2.approx.f32 %0, %1;" : "=f"(d) : "f"(x));
    return d;
}

// ---------------- prep: fp32 -> f16 hi/lo split (elementwise) ---------------
__global__ __launch_bounds__(256) void convert_split_f16(
    const float* __restrict__ src, __half* __restrict__ dh,
    __half* __restrict__ dl, int n4)
{
    int i = blockIdx.x * blockDim.x + threadIdx.x;
    if (i >= n4) return;
    float4 v = *(const float4*)(src + (size_t)i * 4);
    __half h0 = __float2half(v.x), h1 = __float2half(v.y);
    __half h2 = __float2half(v.z), h3 = __float2half(v.w);
    *(uint32_t*)(dh + (size_t)i * 4 + 0) = pack_f16x2(v.x, v.y);
    *(uint32_t*)(dh + (size_t)i * 4 + 2) = pack_f16x2(v.z, v.w);
    *(uint32_t*)(dl + (size_t)i * 4 + 0) =
        pack_f16x2(v.x - __half2float(h0), v.y - __half2float(h1));
    *(uint32_t*)(dl + (size_t)i * 4 + 2) =
        pack_f16x2(v.z - __half2float(h2), v.w - __half2float(h3));
}

// ---------------- prep: transpose weights [K][N] -> [N][K] f16 --------------
__global__ __launch_bounds__(256) void transpose_f16(
    const float* __restrict__ src, __half* __restrict__ dh, int K, int N)
{
    __shared__ float t[32][33];
    int n0 = blockIdx.x * 32, k0 = blockIdx.y * 32;
    int tx = threadIdx.x, ty = threadIdx.y;   // block (32, 8)
    #pragma unroll
    for (int j = ty; j < 32; j += 8)
        t[j][tx] = src[(size_t)(k0 + j) * N + n0 + tx];
    __syncthreads();
    #pragma unroll
    for (int j = ty; j < 32; j += 8)
        dh[(size_t)(n0 + j) * K + k0 + tx] = __float2half(t[tx][j]);
}

// ---------------- 2-term f16 HMMA GEMM (round-16, unchanged) ----------------
#define G_BK        32
#define G_ROWB      80
#define G_TILE_B    (128 * G_ROWB)          // 10240 B
#define G_STAGE_B   (3 * G_TILE_B)          // 30720 B
#define G_SMEM      (2 * G_STAGE_B)         // 61440 B

__global__ __launch_bounds__(128, 2) void gemm_f16_2t(
    const __half* __restrict__ Ah, const __half* __restrict__ Al,
    const __half* __restrict__ Bh,
    const float* __restrict__ bias, float* __restrict__ C, int Ncols, int K)
{
    extern __shared__ char sm[];
    const int tid  = threadIdx.x;
    const int lane = tid & 31;
    const int wid  = tid >> 5;
    const int warp_m = wid >> 1;
    const int warp_n = wid & 1;
    const int g   = lane >> 2;
    const int tig = lane & 3;

    const size_t arow0 = (size_t)blockIdx.y * 128;
    const size_t brow0 = (size_t)blockIdx.x * 128;

    const __half* gA[3] = { Ah + arow0 * K, Al + arow0 * K, Bh + brow0 * K };

    const int lrow = tid >> 2;
    const int c16  = tid & 3;
    auto load_stage = [&](int s, int k0) {
        char* base = sm + s * G_STAGE_B;
        #pragma unroll
        for (int i = 0; i < 12; i++) {
            const int t   = i >> 2;
            const int row = (i & 3) * 32 + lrow;
            const __half* src = gA[t] + (size_t)row * K + k0 + c16 * 8;
            uint32_t dst = smem_u32(base + t * G_TILE_B + row * G_ROWB + c16 * 16);
            CP_ASYNC16(dst, src);
        }
        CP_COMMIT();
    };

    const uint32_t aoff = (uint32_t)((warp_m * 64 + (lane & 15)) * G_ROWB
                                     + (lane >> 4) * 16);
    const uint32_t boff = (uint32_t)((warp_n * 64 + ((lane >> 4) << 3) + (lane & 7)) * G_ROWB
                                     + ((lane >> 3) & 1) * 16);
    const uint32_t smbu = smem_u32(sm);

    float acc[4][8][4];
    #pragma unroll
    for (int mt = 0; mt < 4; mt++)
        #pragma unroll
        for (int nt = 0; nt < 8; nt++)
            #pragma unroll
            for (int i = 0; i < 4; i++) acc[mt][nt][i] = 0.f;

    load_stage(0, 0);

    const int KT = K / G_BK;
    for (int kt = 0; kt < KT; kt++) {
        if (kt + 1 < KT) {
            load_stage((kt + 1) & 1, (kt + 1) * G_BK);
            asm volatile("cp.async.wait_group 1;" ::: "memory");
        } else {
            asm volatile("cp.async.wait_group 0;" ::: "memory");
        }
        __syncthreads();

        const uint32_t sbu  = smbu + (kt & 1) * G_STAGE_B;
        const uint32_t sAhU = sbu + 0 * G_TILE_B + aoff;
        const uint32_t sAlU = sbu + 1 * G_TILE_B + aoff;
        const uint32_t sBhU = sbu + 2 * G_TILE_B + boff;

        #pragma unroll
        for (int ks = 0; ks < 2; ks++) {
            const uint32_t ksb = (uint32_t)(ks * 32);
            uint32_t ah[4][4], al[4][4], bh[4][4];
            #pragma unroll
            for (int np = 0; np < 4; np++)
                ldsm4(bh[np][0], bh[np][1], bh[np][2], bh[np][3],
                      sBhU + np * (16 * G_ROWB) + ksb);
            #pragma unroll
            for (int mt = 0; mt < 4; mt++) {
                ldsm4(ah[mt][0], ah[mt][1], ah[mt][2], ah[mt][3],
                      sAhU + mt * (16 * G_ROWB) + ksb);
                ldsm4(al[mt][0], al[mt][1], al[mt][2], al[mt][3],
                      sAlU + mt * (16 * G_ROWB) + ksb);
            }
            #pragma unroll
            for (int mt = 0; mt < 4; mt++) {
                #pragma unroll
                for (int np = 0; np < 4; np++) {
                    mma16816h(acc[mt][2 * np + 0], ah[mt], &bh[np][0]);
                    mma16816h(acc[mt][2 * np + 1], ah[mt], &bh[np][2]);
                }
                #pragma unroll
                for (int np = 0; np < 4; np++) {
                    mma16816h(acc[mt][2 * np + 0], al[mt], &bh[np][0]);
                    mma16816h(acc[mt][2 * np + 1], al[mt], &bh[np][2]);
                }
            }
        }
        __syncthreads();
    }

    const size_t col0 = (size_t)blockIdx.x * 128 + warp_n * 64;
    #pragma unroll
    for (int mt = 0; mt < 4; mt++) {
        size_t row = arow0 + warp_m * 64 + mt * 16 + g;
        #pragma unroll
        for (int nt = 0; nt < 8; nt++) {
            size_t col = col0 + nt * 8 + tig * 2;
            float b0 = 0.f, b1 = 0.f;
            if (bias) { b0 = bias[col]; b1 = bias[col + 1]; }
            float2 v0 = { acc[mt][nt][0] + b0, acc[mt][nt][1] + b1 };
            float2 v1 = { acc[mt][nt][2] + b0, acc[mt][nt][3] + b1 };
            *(float2*)(C + row * Ncols + col)       = v0;
            *(float2*)(C + (row + 8) * Ncols + col) = v1;
        }
    }
}

// ---------------- HMMA attention: 2-term f16 S (Q split, K single f16) ------
#define AT_THREADS 448
#define KH_STR   72            // K row stride (f16 units)
#define VT_STR   216           // V^T row stride (f16 units)
#define AT_KPAD  208
#define KH_BYTE  (2 * AT_KPAD * KH_STR)              // 29952 (single f16 K)
#define VTH_BYTE KH_BYTE
#define VPART_BYTE (VTH_BYTE + 2 * 72 * VT_STR)      // +31104 = 61056
#define VMEAN_BYTE (VPART_BYTE + 4 * 64 * 4)         // +1024
#define AT_SMEM  (VMEAN_BYTE + 64 * 4)               // 62336 B

#define KS2 0.1803368801111204f   // 0.125 * log2(e)

template<int NCOLS>
__device__ __forceinline__ void attn_chunk(
    const int r0, const int g, const int tig,
    const __half* __restrict__ Khs,
    const __half* __restrict__ Vth,
    const uint32_t (&qh)[4][4], const uint32_t (&ql)[4][4],
    float (&O)[9][4], float (&m_run)[2])
{
    constexpr int NT  = NCOLS / 8;
    constexpr int KSN = NCOLS / 16;
    float S[NT][4];
    #pragma unroll
    for (int nt = 0; nt < NT; nt++)
        S[nt][0] = S[nt][1] = S[nt][2] = S[nt][3] = 0.f;

    #pragma unroll
    for (int nt = 0; nt < NT; nt++) {
        const int krow = r0 + nt * 8 + g;
        #pragma unroll
        for (int ks = 0; ks < 4; ks++) {
            const uint32_t* k32 = (const uint32_t*)(Khs + krow * KH_STR + ks * 16 + tig * 2);
            uint32_t bk[2] = { k32[0], k32[4] };
            mma16816h(S[nt], qh[ks], bk);
            mma16816h(S[nt], ql[ks], bk);
        }
    }
    if (NCOLS == 16) {
        #pragma unroll
        for (int nt = 0; nt < NT; nt++) {
            int col0 = r0 + nt * 8 + tig * 2;
            if (col0 >= NN)     { S[nt][0] = -1e30f; S[nt][2] = -1e30f; }
            if (col0 + 1 >= NN) { S[nt][1] = -1e30f; S[nt][3] = -1e30f; }
        }
    }
    float cm0 = -1e30f, cm1 = -1e30f;
    #pragma unroll
    for (int nt = 0; nt < NT; nt++) {
        cm0 = fmaxf(cm0, fmaxf(S[nt][0], S[nt][1]));
        cm1 = fmaxf(cm1, fmaxf(S[nt][2], S[nt][3]));
    }
    cm0 = fmaxf(cm0, __shfl_xor_sync(0xffffffffu, cm0, 1));
    cm0 = fmaxf(cm0, __shfl_xor_sync(0xffffffffu, cm0, 2));
    cm1 = fmaxf(cm1, __shfl_xor_sync(0xffffffffu, cm1, 1));
    cm1 = fmaxf(cm1, __shfl_xor_sync(0xffffffffu, cm1, 2));

    float mn0 = fmaxf(m_run[0], cm0);
    float mn1 = fmaxf(m_run[1], cm1);
    float a0 = exp2_f32((m_run[0] - mn0) * KS2);
    float a1 = exp2_f32((m_run[1] - mn1) * KS2);
    m_run[0] = mn0; m_run[1] = mn1;
    #pragma unroll
    for (int n2 = 0; n2 < 9; n2++) {
        O[n2][0] *= a0; O[n2][1] *= a0;
        O[n2][2] *= a1; O[n2][3] *= a1;
    }
    const float mk0 = mn0 * KS2, mk1 = mn1 * KS2;
    uint32_t P[NT][2];
    #pragma unroll
    for (int nt = 0; nt < NT; nt++) {
        float t0 = fmaf(S[nt][0], KS2, -mk0);
        float t1 = fmaf(S[nt][1], KS2, -mk0);
        float t2 = fmaf(S[nt][2], KS2, -mk1);
        float t3 = fmaf(S[nt][3], KS2, -mk1);
        P[nt][0] = exp2_f16x2(t0, t1);
        P[nt][1] = exp2_f16x2(t2, t3);
    }
    #pragma unroll
    for (int ks = 0; ks < KSN; ks++) {
        uint32_t A[4] = { P[2*ks][0], P[2*ks][1], P[2*ks+1][0], P[2*ks+1][1] };
        const int kr = r0 + ks * 16 + tig * 2;
        #pragma unroll
        for (int n2 = 0; n2 < 9; n2++) {
            const uint32_t* vh32 = (const uint32_t*)(Vth + (n2 * 8 + g) * VT_STR + kr);
            uint32_t bvh[2] = { vh32[0], vh32[4] };
            mma16816h(O[n2], A, bvh);
        }
    }
}

__global__ __launch_bounds__(AT_THREADS) void attn_hmma(
    const float* __restrict__ qkv,
    __half* __restrict__ yh, __half* __restrict__ yl)
{
    extern __shared__ char smraw[];
    __half* Khs = (__half*)smraw;
    __half* Vth = (__half*)(smraw + VTH_BYTE);
    float* vpart = (float*)(smraw + VPART_BYTE);
    float* vmean = (float*)(smraw + VMEAN_BYTE);

    const int bid = blockIdx.x;
    const int b = bid / (HH * TT);
    const int h = (bid / TT) % HH;
    const int t = bid % TT;
    const size_t row0 = (size_t)b * TNTOK + (size_t)t * NN;

    const float* qbase = qkv + row0 * QKVCOLS + 0 * DD + h * HD;
    const float* kbase = qkv + row0 * QKVCOLS + 1 * DD + h * HD;
    const float* vbase = qkv + row0 * QKVCOLS + 2 * DD + h * HD;

    const int tid  = threadIdx.x;
    const int lane = tid & 31;
    const int w    = tid >> 5;        // 0..13, warp w owns rows [16w, 16w+16)
    const int g    = lane >> 2;
    const int tig  = lane & 3;

    // K -> single f16 (row-major, stride 72)
    for (int idx = tid; idx < NN * 16; idx += AT_THREADS) {
        int row = idx >> 4, d4 = (idx & 15) * 4;
        float4 v = *(const float4*)(kbase + (size_t)row * QKVCOLS + d4);
        *(uint32_t*)(Khs + row * KH_STR + d4)     = pack_f16x2(v.x, v.y);
        *(uint32_t*)(Khs + row * KH_STR + d4 + 2) = pack_f16x2(v.z, v.w);
    }
    // V -> f16, transposed [dim][row] (stride 216)
    for (int idx = tid; idx < NN * HD; idx += AT_THREADS) {
        int row = idx >> 6, dim = idx & 63;
        Vth[dim * VT_STR + row] = __float2half(vbase[(size_t)row * QKVCOLS + dim]);
    }
    // K pad rows 196..207
    for (int idx = tid; idx < 12 * 16; idx += AT_THREADS) {
        int row = NN + (idx >> 4), d4 = (idx & 15) * 4;
        *(uint2*)(Khs + row * KH_STR + d4) = {0u, 0u};
    }
    // V pad rows 196..207 for dims 0..63
    for (int idx = tid; idx < 64 * 12; idx += AT_THREADS) {
        int dim = idx / 12, r = NN + (idx % 12);
        Vth[dim * VT_STR + r] = __ushort_as_half(0);
    }
    // dims 64..71: ones column (dim 64) else zeros
    for (int idx = tid; idx < 8 * AT_KPAD; idx += AT_THREADS) {
        int dim = 64 + idx / AT_KPAD, r = idx % AT_KPAD;
        Vth[dim * VT_STR + r] = (dim == 64) ? __float2half(1.0f) : __ushort_as_half(0);
    }
    __syncthreads();
    if (tid < 256) {
        int part = tid >> 6, dim = tid & 63;
        int rlo = part * 49, rhi = rlo + 49;
        float s = 0.f;
        const __half* vh = Vth + dim * VT_STR;
        for (int r = rlo; r < rhi; r++) s += __half2float(vh[r]);
        vpart[part * 64 + dim] = s;
    }
    __syncthreads();
    if (tid < 64) {
        vmean[tid] = (vpart[tid] + vpart[64 + tid] + vpart[128 + tid] + vpart[192 + tid])
                     * (1.0f / NN);
    }
    __syncthreads();

    int ra = w * 16 + g;
    int rb = ra + 8;
    int rac = (ra > 195) ? 195 : ra;
    int rbc = (rb > 195) ? 195 : rb;

    // Q fragments: f16 hi/lo split from f32
    uint32_t qh[4][4], ql[4][4];
    #pragma unroll
    for (int ks = 0; ks < 4; ks++) {
        #pragma unroll
        for (int hf = 0; hf < 2; hf++) {
            int k = ks * 16 + tig * 2 + hf * 8;
            float2 va = *(const float2*)(qbase + (size_t)rac * QKVCOLS + k);
            float2 vb = *(const float2*)(qbase + (size_t)rbc * QKVCOLS + k);
            __half ha0 = __float2half(va.x), ha1 = __float2half(va.y);
            __half hb0 = __float2half(vb.x), hb1 = __float2half(vb.y);
            qh[ks][hf * 2 + 0] = pack_f16x2(va.x, va.y);
            qh[ks][hf * 2 + 1] = pack_f16x2(vb.x, vb.y);
            ql[ks][hf * 2 + 0] =
                pack_f16x2(va.x - __half2float(ha0), va.y - __half2float(ha1));
            ql[ks][hf * 2 + 1] =
                pack_f16x2(vb.x - __half2float(hb0), vb.y - __half2float(hb1));
        }
    }

    float O[9][4];
    #pragma unroll
    for (int n2 = 0; n2 < 9; n2++)
        O[n2][0] = O[n2][1] = O[n2][2] = O[n2][3] = 0.f;
    float m_run[2] = { -1e30f, -1e30f };

    attn_chunk<64>(  0, g, tig, Khs, Vth, qh, ql, O, m_run);
    attn_chunk<64>( 64, g, tig, Khs, Vth, qh, ql, O, m_run);
    attn_chunk<64>(128, g, tig, Khs, Vth, qh, ql, O, m_run);
    attn_chunk<16>(192, g, tig, Khs, Vth, qh, ql, O, m_run);

    float l0 = __shfl_sync(0xffffffffu, O[8][0], lane & ~3);
    float l1 = __shfl_sync(0xffffffffu, O[8][2], lane & ~3);
    float inv0 = 1.0f / l0, inv1 = 1.0f / l1;
    #pragma unroll
    for (int n2 = 0; n2 < 8; n2++) {
        int dim = n2 * 8 + tig * 2;
        float vm0 = vmean[dim], vm1 = vmean[dim + 1];
        if (ra < NN) {
            float v0 = fmaf(O[n2][0], inv0, vm0);
            float v1 = fmaf(O[n2][1], inv0, vm1);
            __half h0 = __float2half(v0), h1 = __float2half(v1);
            size_t ob = (row0 + ra) * DD + h * HD + dim;
            *(uint32_t*)(yh + ob) = pack_f16x2(v0, v1);
            *(uint32_t*)(yl + ob) = pack_f16x2(v0 - __half2float(h0),
                                               v1 - __half2float(h1));
        }
        if (rb < NN) {
            float v0 = fmaf(O[n2][2], inv1, vm0);
            float v1 = fmaf(O[n2][3], inv1, vm1);
            __half h0 = __float2half(v0), h1 = __float2half(v1);
            size_t ob = (row0 + rb) * DD + h * HD + dim;
            *(uint32_t*)(yh + ob) = pack_f16x2(v0, v1);
            *(uint32_t*)(yl + ob) = pack_f16x2(v0 - __half2float(h0),
                                               v1 - __half2float(h1));
        }
    }
}

// ---------------- launch --------------------------------------------------
extern "C" void kernel_launch(void* const* d_in, const int* in_sizes, int n_in,
                              void* d_out, int out_size)
{
    const float* x = nullptr;
    const float* w_qkv = nullptr;
    const float* w_proj = nullptr;
    const float* b_proj = nullptr;
    for (int i = 0; i < n_in; i++) {
        long sz = in_sizes[i];
        if      (sz == (long)MROWS * DD)   { if (!x) x = (const float*)d_in[i]; }
        else if (sz == (long)DD * QKVCOLS) w_qkv  = (const float*)d_in[i];
        else if (sz == (long)DD * DD)      w_proj = (const float*)d_in[i];
        else if (sz == (long)DD)           b_proj = (const float*)d_in[i];
    }

    void *xh, *xl, *wq, *wp, *qkv, *yh, *yl;
    cudaGetSymbolAddress(&xh, g_xh16);  cudaGetSymbolAddress(&xl, g_xl16);
    cudaGetSymbolAddress(&wq, g_wqkvT16);
    cudaGetSymbolAddress(&wp, g_wprojT16);
    cudaGetSymbolAddress(&qkv, g_qkv);
    cudaGetSymbolAddress(&yh, g_yh16);  cudaGetSymbolAddress(&yl, g_yl16);

    {
        int n4 = MROWS * DD / 4;
        convert_split_f16<<<(n4 + 255) / 256, 256>>>(x, (__half*)xh, (__half*)xl, n4);
        transpose_f16<<<dim3(QKVCOLS / 32, DD / 32), dim3(32, 8)>>>(
            w_qkv, (__half*)wq, DD, QKVCOLS);
        transpose_f16<<<dim3(DD / 32, DD / 32), dim3(32, 8)>>>(
            w_proj, (__half*)wp, DD, DD);
    }

    cudaFuncSetAttribute(gemm_f16_2t, cudaFuncAttributeMaxDynamicSharedMemorySize, G_SMEM);
    cudaFuncSetAttribute(attn_hmma, cudaFuncAttributeMaxDynamicSharedMemorySize, AT_SMEM);

    // 1) QKV projection: (xh+xl)·w16 -> f32 qkv
    gemm_f16_2t<<<dim3(QKVCOLS / 128, MROWS / 128), 128, G_SMEM>>>(
        (const __half*)xh, (const __half*)xl, (const __half*)wq,
        nullptr, (float*)qkv, QKVCOLS, DD);

    // 2) HMMA attention (2-term f16 S), emits f16 hi/lo y
    attn_hmma<<<BB * HH * TT, AT_THREADS, AT_SMEM>>>(
        (const float*)qkv, (__half*)yh, (__half*)yl);

    // 3) output projection + bias: (yh+yl)·wproj16 -> f32 out
    gemm_f16_2t<<<dim3(DD / 128, MROWS / 128), 128, G_SMEM>>>(
        (const __half*)yh, (const __half*)yl, (const __half*)wp,
        b_proj, (float*)d_out, DD, DD);
}